// round 6
// baseline (speedup 1.0000x reference)
#include <cuda_runtime.h>
#include <cuda_fp16.h>
#include <math.h>
#include <stdint.h>

#define NTOK  16384
#define NHEAD 16
#define DHEAD 128
#define HID   512
#define DTOT  2048

typedef __half fh;

// ---------------- scratch (device globals; no allocs allowed) ----------------
static __device__ fh g_xh[(size_t)NTOK * DTOT];
static __device__ fh g_ah[(size_t)NHEAD * NTOK * HID];
static __device__ fh g_al[(size_t)NHEAD * NTOK * HID];
static __device__ fh g_bh[(size_t)NHEAD * NTOK * HID];
static __device__ fh g_w0[(size_t)NHEAD * HID * DHEAD];
static __device__ fh g_w1[(size_t)NHEAD * HID * HID];
static __device__ fh g_w2[(size_t)NHEAD * HID * HID];
static __device__ fh g_w3[(size_t)NHEAD * DHEAD * HID];

// ---------------- helpers ----------------
__device__ __forceinline__ uint32_t smem_u32(const void* p) {
    uint32_t a;
    asm("{ .reg .u64 t; cvta.to.shared.u64 t, %1; cvt.u32.u64 %0, t; }"
        : "=r"(a) : "l"(p));
    return a;
}
__device__ __forceinline__ float gelu_f(float x) {
    return 0.5f * x * (1.0f + erff(x * 0.70710678118654752f));
}
__device__ __forceinline__ void split2h(float v, fh& hi, fh& lo) {
    hi = __float2half_rn(v);
    lo = __float2half_rn(v - __half2float(hi));
}
__device__ __forceinline__ uint32_t packh(fh a, fh b) {
    return (uint32_t)__half_as_ushort(a) | ((uint32_t)__half_as_ushort(b) << 16);
}

__device__ __forceinline__ void ldsm4(uint32_t (&r)[4], uint32_t addr) {
    asm volatile("ldmatrix.sync.aligned.m8n8.x4.shared.b16 {%0,%1,%2,%3}, [%4];"
                 : "=r"(r[0]), "=r"(r[1]), "=r"(r[2]), "=r"(r[3]) : "r"(addr));
}
__device__ __forceinline__ void mma16816(float (&d)[4], const uint32_t (&a)[4],
                                         uint32_t b0, uint32_t b1) {
    asm volatile(
        "mma.sync.aligned.m16n8k16.row.col.f32.f16.f16.f32 "
        "{%0,%1,%2,%3}, {%4,%5,%6,%7}, {%8,%9}, {%0,%1,%2,%3};"
        : "+f"(d[0]), "+f"(d[1]), "+f"(d[2]), "+f"(d[3])
        : "r"(a[0]), "r"(a[1]), "r"(a[2]), "r"(a[3]), "r"(b0), "r"(b1));
}

// cp.async 16B tile loader: ROWS x 64 fp16 (128B rows), XOR-8 chunk swizzle
template <int ROWS>
__device__ __forceinline__ void ldt(uint32_t sbase, const fh* g, int ldg_, int tid) {
#pragma unroll
    for (int q = tid; q < ROWS * 8; q += 256) {
        int r = q >> 3, c8 = q & 7;
        uint32_t dst = sbase + r * 128 + ((c8 ^ (r & 7)) << 4);
        const char* src = (const char*)(g + (size_t)r * ldg_) + c8 * 16;
        asm volatile("cp.async.cg.shared.global [%0], [%1], 16;"
                     :: "r"(dst), "l"(src) : "memory");
    }
}

// =======================================================================
// HMMA fp16 GEMM: D[128x128] = (Ahi [+ Alo])[128xK] @ Bh[128xK]^T
// NTERMS: 1 = single-term A (hi only), 2 = hi+lo split A.
// OMODE:  0 = gelu -> split -> (Ch, Cl) fp16
//         1 = raw fp32 -> Cf
//         2 = gelu -> fp16 hi only -> Ch
// NS: cp.async pipeline stages (3 for 1-term, 2 for 2-term; 96KB either way).
// grid = (M/128, N/128, NHEAD), 256 threads, 2 CTAs/SM.
// =======================================================================
template <int NTERMS, int OMODE, int NS>
__global__ __launch_bounds__(256, 2)
void hgemm_kernel(const fh* __restrict__ Ah, const fh* __restrict__ Al,
                  size_t aHead, int lda,
                  const fh* __restrict__ Bh, size_t bHead, int K,
                  fh* __restrict__ Ch, fh* __restrict__ Cl,
                  float* __restrict__ Cf, size_t cHead, int ldc) {
    extern __shared__ char smem[];
    const uint32_t sb = smem_u32(smem);
    const int tid = threadIdx.x, wid = tid >> 5, lane = tid & 31;
    const int h = blockIdx.z;
    const int m0 = blockIdx.x * 128;
    const int n0 = blockIdx.y * 128;

    constexpr uint32_t TILE = 128 * 128;               // 16KB
    constexpr uint32_t STAGE = (NTERMS + 1) * TILE;    // 32 or 48 KB
    const uint32_t bOff = NTERMS * TILE;               // B tile offset in stage

    const fh* gAh = Ah + h * aHead + (size_t)m0 * lda;
    const fh* gAl = (NTERMS == 2) ? (Al + h * aHead + (size_t)m0 * lda) : nullptr;
    const fh* gBh = Bh + h * bHead + (size_t)n0 * K;

    // warp tile: 64(M) x 32(N); warp grid 2 x 4
    const int wm = (wid & 1) * 64;
    const int wn = (wid >> 1) * 32;

    int arow[4], brow[2];
#pragma unroll
    for (int mi = 0; mi < 4; mi++) arow[mi] = wm + mi * 16 + (lane & 15);
#pragma unroll
    for (int bj = 0; bj < 2; bj++)
        brow[bj] = wn + bj * 16 + ((lane >> 3) & 1) * 8 + (lane & 7);
    const int hi16 = lane >> 4;

    float acc[4][4][4];
#pragma unroll
    for (int i = 0; i < 4; i++)
#pragma unroll
        for (int j = 0; j < 4; j++)
#pragma unroll
            for (int e = 0; e < 4; e++) acc[i][j][e] = 0.f;

    const int KT = K >> 6;

    // preload stages 0..NS-2 (one commit group per stage)
#pragma unroll
    for (int p = 0; p < NS - 1; p++) {
        if (p < KT) {
            const uint32_t st = sb + (uint32_t)p * STAGE;
            const int k0 = p * 64;
            ldt<128>(st, gAh + k0, lda, tid);
            if (NTERMS == 2) ldt<128>(st + TILE, gAl + k0, lda, tid);
            ldt<128>(st + bOff, gBh + k0, K, tid);
        }
        asm volatile("cp.async.commit_group;" ::: "memory");
    }

    for (int c = 0; c < KT; c++) {
        // issue loads for stage c+NS-1 (possibly empty), one group per iter
        {
            const int cn = c + NS - 1;
            if (cn < KT) {
                const uint32_t sn = sb + (uint32_t)(cn % NS) * STAGE;
                const int k0 = cn * 64;
                ldt<128>(sn, gAh + k0, lda, tid);
                if (NTERMS == 2) ldt<128>(sn + TILE, gAl + k0, lda, tid);
                ldt<128>(sn + bOff, gBh + k0, K, tid);
            }
            asm volatile("cp.async.commit_group;" ::: "memory");
        }
        // wait until stage c's group is complete (keep NS-1 groups in flight)
        asm volatile("cp.async.wait_group %0;" :: "n"(NS - 1) : "memory");
        __syncthreads();

        const uint32_t st = sb + (uint32_t)(c % NS) * STAGE;
#pragma unroll
        for (int s = 0; s < 4; s++) {
            uint32_t ahf[4][4], alf[4][4], bhf[2][4];
            const int c2 = s * 2 + hi16;
#pragma unroll
            for (int mi = 0; mi < 4; mi++) {
                const uint32_t ao = arow[mi] * 128 + ((c2 ^ (arow[mi] & 7)) << 4);
                ldsm4(ahf[mi], st + ao);
                if (NTERMS == 2) ldsm4(alf[mi], st + TILE + ao);
            }
#pragma unroll
            for (int bj = 0; bj < 2; bj++) {
                const uint32_t bo = brow[bj] * 128 + ((c2 ^ (brow[bj] & 7)) << 4);
                ldsm4(bhf[bj], st + bOff + bo);
            }
#pragma unroll
            for (int mi = 0; mi < 4; mi++)
#pragma unroll
                for (int bj = 0; bj < 2; bj++) {
                    mma16816(acc[mi][2 * bj],     ahf[mi], bhf[bj][0], bhf[bj][2]);
                    mma16816(acc[mi][2 * bj + 1], ahf[mi], bhf[bj][1], bhf[bj][3]);
                }
            if (NTERMS == 2) {
#pragma unroll
                for (int mi = 0; mi < 4; mi++)
#pragma unroll
                    for (int bj = 0; bj < 2; bj++) {
                        mma16816(acc[mi][2 * bj],     alf[mi], bhf[bj][0], bhf[bj][2]);
                        mma16816(acc[mi][2 * bj + 1], alf[mi], bhf[bj][1], bhf[bj][3]);
                    }
            }
        }
        __syncthreads();
    }

    // ---------------- epilogue ----------------
    const int rbase = (lane >> 2);
    const int cbase = (lane & 3) * 2;

#pragma unroll
    for (int mi = 0; mi < 4; mi++) {
#pragma unroll
        for (int nj = 0; nj < 4; nj++) {
#pragma unroll
            for (int half = 0; half < 2; half++) {
                const size_t m = (size_t)m0 + wm + mi * 16 + rbase + half * 8;
                const int col = n0 + wn + nj * 8 + cbase;
                float v0 = acc[mi][nj][2 * half];
                float v1 = acc[mi][nj][2 * half + 1];
                if (OMODE == 0) {
                    v0 = gelu_f(v0);
                    v1 = gelu_f(v1);
                    fh h0, l0, h1, l1;
                    split2h(v0, h0, l0);
                    split2h(v1, h1, l1);
                    *reinterpret_cast<uint32_t*>(Ch + h * cHead + m * ldc + col) =
                        packh(h0, h1);
                    *reinterpret_cast<uint32_t*>(Cl + h * cHead + m * ldc + col) =
                        packh(l0, l1);
                } else if (OMODE == 2) {
                    v0 = gelu_f(v0);
                    v1 = gelu_f(v1);
                    *reinterpret_cast<uint32_t*>(Ch + h * cHead + m * ldc + col) =
                        packh(__float2half_rn(v0), __float2half_rn(v1));
                } else {
                    *reinterpret_cast<float2*>(Cf + h * cHead + m * ldc + col) =
                        make_float2(v0, v1);
                }
            }
        }
    }
}

// ---------------- RMSNorm -> fp16 (hi only) ----------------
__global__ void rms_kernel(const float* __restrict__ x, const float* __restrict__ g,
                           fh* __restrict__ xh) {
    const int row = blockIdx.x, tid = threadIdx.x;
    const float4* xr = reinterpret_cast<const float4*>(x + (size_t)row * DTOT);
    float4 a = xr[tid], b = xr[tid + 256];
    float s = a.x * a.x + a.y * a.y + a.z * a.z + a.w * a.w +
              b.x * b.x + b.y * b.y + b.z * b.z + b.w * b.w;
#pragma unroll
    for (int o = 16; o; o >>= 1) s += __shfl_xor_sync(0xffffffffu, s, o);
    __shared__ float ws[8];
    __shared__ float srs;
    if ((tid & 31) == 0) ws[tid >> 5] = s;
    __syncthreads();
    if (tid == 0) {
        float t = 0.f;
#pragma unroll
        for (int i = 0; i < 8; i++) t += ws[i];
        srs = rsqrtf(t * (1.0f / DTOT) + 1.1920929e-7f);
    }
    __syncthreads();
    const float rs = srs;
    const float4* gr = reinterpret_cast<const float4*>(g);
    float4 ga = gr[tid], gb = gr[tid + 256];

    float va[8] = {a.x * rs * ga.x, a.y * rs * ga.y, a.z * rs * ga.z, a.w * rs * ga.w,
                   b.x * rs * gb.x, b.y * rs * gb.y, b.z * rs * gb.z, b.w * rs * gb.w};
    size_t base = (size_t)row * DTOT;
#pragma unroll
    for (int half = 0; half < 2; half++) {
        size_t o = base + (size_t)(tid + half * 256) * 4;
        uint32_t hp[2];
#pragma unroll
        for (int j = 0; j < 2; j++)
            hp[j] = packh(__float2half_rn(va[half * 4 + 2 * j]),
                          __float2half_rn(va[half * 4 + 2 * j + 1]));
        *reinterpret_cast<uint2*>(xh + o) = make_uint2(hp[0], hp[1]);
    }
}

// ---------------- weight transpose to fp16: W[h][K][N] -> O[h][N][K] ----------------
__global__ void wsplit_kernel(const float* __restrict__ W, int K, int N,
                              fh* __restrict__ Oh) {
    __shared__ float t[32][33];
    const int h = blockIdx.z;
    const int k0 = blockIdx.x * 32, n0 = blockIdx.y * 32;
    const int tx = threadIdx.x & 31, ty = threadIdx.x >> 5;
    const float* Wb = W + (size_t)h * K * N;
#pragma unroll
    for (int i = 0; i < 4; i++)
        t[ty + i * 8][tx] = Wb[(size_t)(k0 + ty + i * 8) * N + n0 + tx];
    __syncthreads();
#pragma unroll
    for (int i = 0; i < 4; i++) {
        int n = n0 + ty + i * 8, k = k0 + tx;
        size_t o = ((size_t)h * N + n) * K + k;
        Oh[o] = __float2half_rn(t[tx][ty + i * 8]);
    }
}

// ---------------- launch ----------------
extern "C" void kernel_launch(void* const* d_in, const int* in_sizes, int n_in,
                              void* d_out, int out_size) {
    const float* x  = (const float*)d_in[0];
    const float* g  = (const float*)d_in[1];
    const float* w0 = (const float*)d_in[2];
    const float* w1 = (const float*)d_in[3];
    const float* w2 = (const float*)d_in[4];
    const float* w3 = (const float*)d_in[5];
    float* out = (float*)d_out;

    fh *xh, *ah, *al, *bh, *pw0, *pw1, *pw2, *pw3;
    cudaGetSymbolAddress((void**)&xh, g_xh);
    cudaGetSymbolAddress((void**)&ah, g_ah);
    cudaGetSymbolAddress((void**)&al, g_al);
    cudaGetSymbolAddress((void**)&bh, g_bh);
    cudaGetSymbolAddress((void**)&pw0, g_w0);
    cudaGetSymbolAddress((void**)&pw1, g_w1);
    cudaGetSymbolAddress((void**)&pw2, g_w2);
    cudaGetSymbolAddress((void**)&pw3, g_w3);

    constexpr int SMEM1 = 3 * 2 * 128 * 128;  // 96KB: 1-term, 3 stages
    constexpr int SMEM2 = 2 * 3 * 128 * 128;  // 96KB: 2-term, 2 stages
    cudaFuncSetAttribute(hgemm_kernel<1, 2, 3>,
                         cudaFuncAttributeMaxDynamicSharedMemorySize, SMEM1);
    cudaFuncSetAttribute(hgemm_kernel<1, 0, 3>,
                         cudaFuncAttributeMaxDynamicSharedMemorySize, SMEM1);
    cudaFuncSetAttribute(hgemm_kernel<2, 1, 2>,
                         cudaFuncAttributeMaxDynamicSharedMemorySize, SMEM2);

    // prep
    rms_kernel<<<NTOK, 256>>>(x, g, xh);
    wsplit_kernel<<<dim3(DHEAD / 32, HID / 32, NHEAD), 256>>>(w0, DHEAD, HID, pw0);
    wsplit_kernel<<<dim3(HID / 32, HID / 32, NHEAD), 256>>>(w1, HID, HID, pw1);
    wsplit_kernel<<<dim3(HID / 32, HID / 32, NHEAD), 256>>>(w2, HID, HID, pw2);
    wsplit_kernel<<<dim3(HID / 32, DHEAD / 32, NHEAD), 256>>>(w3, HID, DHEAD, pw3);

    const size_t actHead = (size_t)NTOK * HID;

    // L0: a = gelu( xn[:,h] @ w0[h] )   1-term in, hi-only out
    hgemm_kernel<1, 2, 3><<<dim3(NTOK / 128, HID / 128, NHEAD), 256, SMEM1>>>(
        xh, nullptr, (size_t)DHEAD, DTOT, pw0, (size_t)HID * DHEAD, DHEAD,
        ah, nullptr, nullptr, actHead, HID);
    // L1: b = gelu( a @ w1[h] )         1-term in, hi-only out
    hgemm_kernel<1, 2, 3><<<dim3(NTOK / 128, HID / 128, NHEAD), 256, SMEM1>>>(
        ah, nullptr, actHead, HID, pw1, (size_t)HID * HID, HID,
        bh, nullptr, nullptr, actHead, HID);
    // L2: a = gelu( b @ w2[h] )         1-term in, split out (L3 is 2-term)
    hgemm_kernel<1, 0, 3><<<dim3(NTOK / 128, HID / 128, NHEAD), 256, SMEM1>>>(
        bh, nullptr, actHead, HID, pw2, (size_t)HID * HID, HID,
        ah, al, nullptr, actHead, HID);
    // L3: out[:,h] = a @ w3[h]          2-term in, fp32 out, no gelu
    hgemm_kernel<2, 1, 2><<<dim3(NTOK / 128, DHEAD / 128, NHEAD), 256, SMEM2>>>(
        ah, al, actHead, HID, pw3, (size_t)DHEAD * HID, HID,
        nullptr, nullptr, out, (size_t)DHEAD, DTOT);
}

// round 7
// speedup vs baseline: 1.0282x; 1.0282x over previous
#include <cuda_runtime.h>
#include <cuda_fp16.h>
#include <math.h>
#include <stdint.h>

#define NTOK  16384
#define NHEAD 16
#define DHEAD 128
#define HID   512
#define DTOT  2048

typedef __half fh;

// ---------------- scratch (device globals; no allocs allowed) ----------------
static __device__ fh g_xh[(size_t)NTOK * DTOT];
static __device__ fh g_ah[(size_t)NHEAD * NTOK * HID];
static __device__ fh g_bh[(size_t)NHEAD * NTOK * HID];
static __device__ fh g_w0[(size_t)NHEAD * HID * DHEAD];
static __device__ fh g_w1[(size_t)NHEAD * HID * HID];
static __device__ fh g_w2[(size_t)NHEAD * HID * HID];
static __device__ fh g_w3[(size_t)NHEAD * DHEAD * HID];

// ---------------- helpers ----------------
__device__ __forceinline__ uint32_t smem_u32(const void* p) {
    uint32_t a;
    asm("{ .reg .u64 t; cvta.to.shared.u64 t, %1; cvt.u32.u64 %0, t; }"
        : "=r"(a) : "l"(p));
    return a;
}
__device__ __forceinline__ float gelu_f(float x) {
    return 0.5f * x * (1.0f + erff(x * 0.70710678118654752f));
}
__device__ __forceinline__ uint32_t packh(fh a, fh b) {
    return (uint32_t)__half_as_ushort(a) | ((uint32_t)__half_as_ushort(b) << 16);
}

__device__ __forceinline__ void ldsm4(uint32_t (&r)[4], uint32_t addr) {
    asm volatile("ldmatrix.sync.aligned.m8n8.x4.shared.b16 {%0,%1,%2,%3}, [%4];"
                 : "=r"(r[0]), "=r"(r[1]), "=r"(r[2]), "=r"(r[3]) : "r"(addr));
}
__device__ __forceinline__ void mma16816(float (&d)[4], const uint32_t (&a)[4],
                                         uint32_t b0, uint32_t b1) {
    asm volatile(
        "mma.sync.aligned.m16n8k16.row.col.f32.f16.f16.f32 "
        "{%0,%1,%2,%3}, {%4,%5,%6,%7}, {%8,%9}, {%0,%1,%2,%3};"
        : "+f"(d[0]), "+f"(d[1]), "+f"(d[2]), "+f"(d[3])
        : "r"(a[0]), "r"(a[1]), "r"(a[2]), "r"(a[3]), "r"(b0), "r"(b1));
}

// cp.async 16B tile loader: ROWS x 64 fp16 (128B rows), XOR-8 chunk swizzle
template <int ROWS>
__device__ __forceinline__ void ldt(uint32_t sbase, const fh* g, int ldg_, int tid) {
#pragma unroll
    for (int q = tid; q < ROWS * 8; q += 256) {
        int r = q >> 3, c8 = q & 7;
        uint32_t dst = sbase + r * 128 + ((c8 ^ (r & 7)) << 4);
        const char* src = (const char*)(g + (size_t)r * ldg_) + c8 * 16;
        asm volatile("cp.async.cg.shared.global [%0], [%1], 16;"
                     :: "r"(dst), "l"(src) : "memory");
    }
}

// =======================================================================
// HMMA fp16 1-term GEMM: D[128 x BN] = Ah[128xK] @ Bh[BN x K]^T
// BN: 256 -> warp tile 64x64 (1 CTA/SM), 128 -> warp tile 64x32 (2 CTA/SM)
// OMODE: 1 = raw fp32 -> Cf, 2 = gelu -> fp16 -> Ch
// NS: cp.async stages. 256 threads, warp grid 2(M) x 4(N).
// =======================================================================
template <int BN, int OMODE, int NS, int OCC>
__global__ __launch_bounds__(256, OCC)
void hgemm_kernel(const fh* __restrict__ Ah, size_t aHead, int lda,
                  const fh* __restrict__ Bh, size_t bHead, int K,
                  fh* __restrict__ Ch, float* __restrict__ Cf,
                  size_t cHead, int ldc) {
    extern __shared__ char smem[];
    const uint32_t sb = smem_u32(smem);
    const int tid = threadIdx.x, wid = tid >> 5, lane = tid & 31;
    const int h = blockIdx.z;
    const int m0 = blockIdx.x * 128;
    const int n0 = blockIdx.y * BN;

    constexpr int WN  = BN / 4;          // warp tile N: 64 or 32
    constexpr int NBJ = WN / 16;         // B ldsm.x4 count: 4 or 2
    constexpr uint32_t TILE_A = 128 * 128;           // 16KB
    constexpr uint32_t TILE_B = (uint32_t)BN * 128;  // 32KB or 16KB
    constexpr uint32_t STAGE = TILE_A + TILE_B;

    const fh* gAh = Ah + h * aHead + (size_t)m0 * lda;
    const fh* gBh = Bh + h * bHead + (size_t)n0 * K;

    const int wm = (wid & 1) * 64;
    const int wn = (wid >> 1) * WN;

    int arow[4], brow[NBJ];
#pragma unroll
    for (int mi = 0; mi < 4; mi++) arow[mi] = wm + mi * 16 + (lane & 15);
#pragma unroll
    for (int bj = 0; bj < NBJ; bj++)
        brow[bj] = wn + bj * 16 + ((lane >> 3) & 1) * 8 + (lane & 7);
    const int hi16 = lane >> 4;

    float acc[4][2 * NBJ][4];
#pragma unroll
    for (int i = 0; i < 4; i++)
#pragma unroll
        for (int j = 0; j < 2 * NBJ; j++)
#pragma unroll
            for (int e = 0; e < 4; e++) acc[i][j][e] = 0.f;

    const int KT = K >> 6;

    // preload stages 0..NS-2
#pragma unroll
    for (int p = 0; p < NS - 1; p++) {
        if (p < KT) {
            const uint32_t st = sb + (uint32_t)p * STAGE;
            const int k0 = p * 64;
            ldt<128>(st, gAh + k0, lda, tid);
            ldt<BN>(st + TILE_A, gBh + k0, K, tid);
        }
        asm volatile("cp.async.commit_group;" ::: "memory");
    }

    for (int c = 0; c < KT; c++) {
        {
            const int cn = c + NS - 1;
            if (cn < KT) {
                const uint32_t sn = sb + (uint32_t)(cn % NS) * STAGE;
                const int k0 = cn * 64;
                ldt<128>(sn, gAh + k0, lda, tid);
                ldt<BN>(sn + TILE_A, gBh + k0, K, tid);
            }
            asm volatile("cp.async.commit_group;" ::: "memory");
        }
        asm volatile("cp.async.wait_group %0;" :: "n"(NS - 1) : "memory");
        __syncthreads();

        const uint32_t st = sb + (uint32_t)(c % NS) * STAGE;
#pragma unroll
        for (int s = 0; s < 4; s++) {
            uint32_t ahf[4][4], bhf[NBJ][4];
            const int c2 = s * 2 + hi16;
#pragma unroll
            for (int mi = 0; mi < 4; mi++) {
                const uint32_t ao = arow[mi] * 128 + ((c2 ^ (arow[mi] & 7)) << 4);
                ldsm4(ahf[mi], st + ao);
            }
#pragma unroll
            for (int bj = 0; bj < NBJ; bj++) {
                const uint32_t bo = brow[bj] * 128 + ((c2 ^ (brow[bj] & 7)) << 4);
                ldsm4(bhf[bj], st + TILE_A + bo);
            }
#pragma unroll
            for (int mi = 0; mi < 4; mi++)
#pragma unroll
                for (int bj = 0; bj < NBJ; bj++) {
                    mma16816(acc[mi][2 * bj],     ahf[mi], bhf[bj][0], bhf[bj][2]);
                    mma16816(acc[mi][2 * bj + 1], ahf[mi], bhf[bj][1], bhf[bj][3]);
                }
        }
        __syncthreads();
    }

    // ---------------- epilogue ----------------
    const int rbase = (lane >> 2);
    const int cbase = (lane & 3) * 2;

#pragma unroll
    for (int mi = 0; mi < 4; mi++) {
#pragma unroll
        for (int nj = 0; nj < 2 * NBJ; nj++) {
#pragma unroll
            for (int half = 0; half < 2; half++) {
                const size_t m = (size_t)m0 + wm + mi * 16 + rbase + half * 8;
                const int col = n0 + wn + nj * 8 + cbase;
                float v0 = acc[mi][nj][2 * half];
                float v1 = acc[mi][nj][2 * half + 1];
                if (OMODE == 2) {
                    v0 = gelu_f(v0);
                    v1 = gelu_f(v1);
                    *reinterpret_cast<uint32_t*>(Ch + h * cHead + m * ldc + col) =
                        packh(__float2half_rn(v0), __float2half_rn(v1));
                } else {
                    *reinterpret_cast<float2*>(Cf + h * cHead + m * ldc + col) =
                        make_float2(v0, v1);
                }
            }
        }
    }
}

// ---------------- RMSNorm -> fp16 (hi only) ----------------
__global__ void rms_kernel(const float* __restrict__ x, const float* __restrict__ g,
                           fh* __restrict__ xh) {
    const int row = blockIdx.x, tid = threadIdx.x;
    const float4* xr = reinterpret_cast<const float4*>(x + (size_t)row * DTOT);
    float4 a = xr[tid], b = xr[tid + 256];
    float s = a.x * a.x + a.y * a.y + a.z * a.z + a.w * a.w +
              b.x * b.x + b.y * b.y + b.z * b.z + b.w * b.w;
#pragma unroll
    for (int o = 16; o; o >>= 1) s += __shfl_xor_sync(0xffffffffu, s, o);
    __shared__ float ws[8];
    __shared__ float srs;
    if ((tid & 31) == 0) ws[tid >> 5] = s;
    __syncthreads();
    if (tid == 0) {
        float t = 0.f;
#pragma unroll
        for (int i = 0; i < 8; i++) t += ws[i];
        srs = rsqrtf(t * (1.0f / DTOT) + 1.1920929e-7f);
    }
    __syncthreads();
    const float rs = srs;
    const float4* gr = reinterpret_cast<const float4*>(g);
    float4 ga = gr[tid], gb = gr[tid + 256];

    float va[8] = {a.x * rs * ga.x, a.y * rs * ga.y, a.z * rs * ga.z, a.w * rs * ga.w,
                   b.x * rs * gb.x, b.y * rs * gb.y, b.z * rs * gb.z, b.w * rs * gb.w};
    size_t base = (size_t)row * DTOT;
#pragma unroll
    for (int half = 0; half < 2; half++) {
        size_t o = base + (size_t)(tid + half * 256) * 4;
        uint32_t hp[2];
#pragma unroll
        for (int j = 0; j < 2; j++)
            hp[j] = packh(__float2half_rn(va[half * 4 + 2 * j]),
                          __float2half_rn(va[half * 4 + 2 * j + 1]));
        *reinterpret_cast<uint2*>(xh + o) = make_uint2(hp[0], hp[1]);
    }
}

// ---------------- weight transpose to fp16: W[h][K][N] -> O[h][N][K] ----------------
__global__ void wsplit_kernel(const float* __restrict__ W, int K, int N,
                              fh* __restrict__ Oh) {
    __shared__ float t[32][33];
    const int h = blockIdx.z;
    const int k0 = blockIdx.x * 32, n0 = blockIdx.y * 32;
    const int tx = threadIdx.x & 31, ty = threadIdx.x >> 5;
    const float* Wb = W + (size_t)h * K * N;
#pragma unroll
    for (int i = 0; i < 4; i++)
        t[ty + i * 8][tx] = Wb[(size_t)(k0 + ty + i * 8) * N + n0 + tx];
    __syncthreads();
#pragma unroll
    for (int i = 0; i < 4; i++) {
        int n = n0 + ty + i * 8, k = k0 + tx;
        size_t o = ((size_t)h * N + n) * K + k;
        Oh[o] = __float2half_rn(t[tx][ty + i * 8]);
    }
}

// ---------------- launch ----------------
extern "C" void kernel_launch(void* const* d_in, const int* in_sizes, int n_in,
                              void* d_out, int out_size) {
    const float* x  = (const float*)d_in[0];
    const float* g  = (const float*)d_in[1];
    const float* w0 = (const float*)d_in[2];
    const float* w1 = (const float*)d_in[3];
    const float* w2 = (const float*)d_in[4];
    const float* w3 = (const float*)d_in[5];
    float* out = (float*)d_out;

    fh *xh, *ah, *bh, *pw0, *pw1, *pw2, *pw3;
    cudaGetSymbolAddress((void**)&xh, g_xh);
    cudaGetSymbolAddress((void**)&ah, g_ah);
    cudaGetSymbolAddress((void**)&bh, g_bh);
    cudaGetSymbolAddress((void**)&pw0, g_w0);
    cudaGetSymbolAddress((void**)&pw1, g_w1);
    cudaGetSymbolAddress((void**)&pw2, g_w2);
    cudaGetSymbolAddress((void**)&pw3, g_w3);

    constexpr int SMEM256 = 3 * (128 * 128 + 256 * 128);  // 147456: BN=256, 3 stages
    constexpr int SMEM128 = 3 * (128 * 128 + 128 * 128);  // 98304:  BN=128, 3 stages
    cudaFuncSetAttribute(hgemm_kernel<256, 2, 3, 1>,
                         cudaFuncAttributeMaxDynamicSharedMemorySize, SMEM256);
    cudaFuncSetAttribute(hgemm_kernel<128, 1, 3, 2>,
                         cudaFuncAttributeMaxDynamicSharedMemorySize, SMEM128);

    // prep
    rms_kernel<<<NTOK, 256>>>(x, g, xh);
    wsplit_kernel<<<dim3(DHEAD / 32, HID / 32, NHEAD), 256>>>(w0, DHEAD, HID, pw0);
    wsplit_kernel<<<dim3(HID / 32, HID / 32, NHEAD), 256>>>(w1, HID, HID, pw1);
    wsplit_kernel<<<dim3(HID / 32, HID / 32, NHEAD), 256>>>(w2, HID, HID, pw2);
    wsplit_kernel<<<dim3(HID / 32, DHEAD / 32, NHEAD), 256>>>(w3, HID, DHEAD, pw3);

    const size_t actHead = (size_t)NTOK * HID;

    // L0: a = gelu( xn[:,h] @ w0[h] )   BN=256 fat tile
    hgemm_kernel<256, 2, 3, 1><<<dim3(NTOK / 128, HID / 256, NHEAD), 256, SMEM256>>>(
        xh, (size_t)DHEAD, DTOT, pw0, (size_t)HID * DHEAD, DHEAD,
        ah, nullptr, actHead, HID);
    // L1: b = gelu( a @ w1[h] )
    hgemm_kernel<256, 2, 3, 1><<<dim3(NTOK / 128, HID / 256, NHEAD), 256, SMEM256>>>(
        ah, actHead, HID, pw1, (size_t)HID * HID, HID,
        bh, nullptr, actHead, HID);
    // L2: a = gelu( b @ w2[h] )
    hgemm_kernel<256, 2, 3, 1><<<dim3(NTOK / 128, HID / 256, NHEAD), 256, SMEM256>>>(
        bh, actHead, HID, pw2, (size_t)HID * HID, HID,
        ah, nullptr, actHead, HID);
    // L3: out[:,h] = a @ w3[h]   BN=128, fp32 out, no gelu
    hgemm_kernel<128, 1, 3, 2><<<dim3(NTOK / 128, DHEAD / 128, NHEAD), 256, SMEM128>>>(
        ah, actHead, HID, pw3, (size_t)DHEAD * HID, HID,
        nullptr, out, (size_t)DHEAD, DTOT);
}

// round 8
// speedup vs baseline: 1.1263x; 1.0954x over previous
#include <cuda_runtime.h>
#include <cuda_fp16.h>
#include <math.h>
#include <stdint.h>

#define NTOK  16384
#define NHEAD 16
#define DHEAD 128
#define HID   512
#define DTOT  2048

typedef __half fh;

// ---------------- scratch (device globals; no allocs allowed) ----------------
static __device__ fh g_xh[(size_t)NTOK * DTOT];
static __device__ fh g_ah[(size_t)NHEAD * NTOK * HID];
static __device__ fh g_bh[(size_t)NHEAD * NTOK * HID];
static __device__ fh g_w0[(size_t)NHEAD * HID * DHEAD];
static __device__ fh g_w1[(size_t)NHEAD * HID * HID];
static __device__ fh g_w2[(size_t)NHEAD * HID * HID];
static __device__ fh g_w3[(size_t)NHEAD * DHEAD * HID];

// ---------------- helpers ----------------
__device__ __forceinline__ uint32_t smem_u32(const void* p) {
    uint32_t a;
    asm("{ .reg .u64 t; cvta.to.shared.u64 t, %1; cvt.u32.u64 %0, t; }"
        : "=r"(a) : "l"(p));
    return a;
}
__device__ __forceinline__ float gelu_f(float x) {
    return 0.5f * x * (1.0f + erff(x * 0.70710678118654752f));
}
__device__ __forceinline__ uint32_t packh(fh a, fh b) {
    return (uint32_t)__half_as_ushort(a) | ((uint32_t)__half_as_ushort(b) << 16);
}

__device__ __forceinline__ void ldsm4(uint32_t (&r)[4], uint32_t addr) {
    asm volatile("ldmatrix.sync.aligned.m8n8.x4.shared.b16 {%0,%1,%2,%3}, [%4];"
                 : "=r"(r[0]), "=r"(r[1]), "=r"(r[2]), "=r"(r[3]) : "r"(addr));
}
__device__ __forceinline__ void mma16816(float (&d)[4], const uint32_t (&a)[4],
                                         uint32_t b0, uint32_t b1) {
    asm volatile(
        "mma.sync.aligned.m16n8k16.row.col.f32.f16.f16.f32 "
        "{%0,%1,%2,%3}, {%4,%5,%6,%7}, {%8,%9}, {%0,%1,%2,%3};"
        : "+f"(d[0]), "+f"(d[1]), "+f"(d[2]), "+f"(d[3])
        : "r"(a[0]), "r"(a[1]), "r"(a[2]), "r"(a[3]), "r"(b0), "r"(b1));
}

// cp.async 16B tile loader: ROWS x 64 fp16 (128B rows), XOR-8 chunk swizzle
template <int ROWS>
__device__ __forceinline__ void ldt(uint32_t sbase, const fh* g, int ldg_, int tid) {
#pragma unroll
    for (int q = tid; q < ROWS * 8; q += 256) {
        int r = q >> 3, c8 = q & 7;
        uint32_t dst = sbase + r * 128 + ((c8 ^ (r & 7)) << 4);
        const char* src = (const char*)(g + (size_t)r * ldg_) + c8 * 16;
        asm volatile("cp.async.cg.shared.global [%0], [%1], 16;"
                     :: "r"(dst), "l"(src) : "memory");
    }
}

// =======================================================================
// HMMA fp16 1-term GEMM: D[128 x BN] = Ah[128xK] @ Bh[BN x K]^T
// BN=256: warp tile 64x64, 1 CTA/SM, register-double-buffered fragments
//         with cross-chunk prefetch (FRAGDB=1, NS=3).
// BN=128: warp tile 64x32, 2 CTA/SM, simple path (FRAGDB=0).
// OMODE: 1 = raw fp32 -> Cf, 2 = gelu -> fp16 -> Ch
// =======================================================================
template <int BN, int OMODE, int NS, int OCC, int FRAGDB>
__global__ __launch_bounds__(256, OCC)
void hgemm_kernel(const fh* __restrict__ Ah, size_t aHead, int lda,
                  const fh* __restrict__ Bh, size_t bHead, int K,
                  fh* __restrict__ Ch, float* __restrict__ Cf,
                  size_t cHead, int ldc) {
    extern __shared__ char smem[];
    const uint32_t sb = smem_u32(smem);
    const int tid = threadIdx.x, wid = tid >> 5, lane = tid & 31;
    const int h = blockIdx.z;
    const int m0 = blockIdx.x * 128;
    const int n0 = blockIdx.y * BN;

    constexpr int WN  = BN / 4;          // warp tile N: 64 or 32
    constexpr int NBJ = WN / 16;         // B ldsm.x4 count: 4 or 2
    constexpr uint32_t TILE_A = 128 * 128;
    constexpr uint32_t TILE_B = (uint32_t)BN * 128;
    constexpr uint32_t STAGE = TILE_A + TILE_B;

    const fh* gAh = Ah + h * aHead + (size_t)m0 * lda;
    const fh* gBh = Bh + h * bHead + (size_t)n0 * K;

    const int wm = (wid & 1) * 64;
    const int wn = (wid >> 1) * WN;

    int arow[4], brow[NBJ];
#pragma unroll
    for (int mi = 0; mi < 4; mi++) arow[mi] = wm + mi * 16 + (lane & 15);
#pragma unroll
    for (int bj = 0; bj < NBJ; bj++)
        brow[bj] = wn + bj * 16 + ((lane >> 3) & 1) * 8 + (lane & 7);
    const int hi16 = lane >> 4;

    float acc[4][2 * NBJ][4];
#pragma unroll
    for (int i = 0; i < 4; i++)
#pragma unroll
        for (int j = 0; j < 2 * NBJ; j++)
#pragma unroll
            for (int e = 0; e < 4; e++) acc[i][j][e] = 0.f;

    const int KT = K >> 6;

    // preload stages 0..NS-2
#pragma unroll
    for (int p = 0; p < NS - 1; p++) {
        if (p < KT) {
            const uint32_t st = sb + (uint32_t)p * STAGE;
            const int k0 = p * 64;
            ldt<128>(st, gAh + k0, lda, tid);
            ldt<BN>(st + TILE_A, gBh + k0, K, tid);
        }
        asm volatile("cp.async.commit_group;" ::: "memory");
    }

    if (FRAGDB) {
        // ---- register-double-buffered path ----
        uint32_t ahf[2][4][4], bhf[2][NBJ][4];

#define LOADFRAGS(buf, stbase, sstep)                                           \
        do {                                                                    \
            const int c2_ = (sstep) * 2 + hi16;                                 \
            _Pragma("unroll")                                                   \
            for (int mi_ = 0; mi_ < 4; mi_++)                                   \
                ldsm4(ahf[buf][mi_],                                            \
                      (stbase) + arow[mi_] * 128 +                              \
                      ((c2_ ^ (arow[mi_] & 7)) << 4));                          \
            _Pragma("unroll")                                                   \
            for (int bj_ = 0; bj_ < NBJ; bj_++)                                 \
                ldsm4(bhf[buf][bj_],                                            \
                      (stbase) + TILE_A + brow[bj_] * 128 +                     \
                      ((c2_ ^ (brow[bj_] & 7)) << 4));                          \
        } while (0)

        // prime: stage 0 complete, fragments for (chunk 0, s=0)
        asm volatile("cp.async.wait_group %0;" :: "n"(NS - 2) : "memory");
        __syncthreads();
        LOADFRAGS(0, sb, 0);

        for (int c = 0; c < KT; c++) {
            const uint32_t st = sb + (uint32_t)(c % NS) * STAGE;
            {
                const int cn = c + NS - 1;
                if (cn < KT) {
                    const uint32_t sn = sb + (uint32_t)(cn % NS) * STAGE;
                    const int k0 = cn * 64;
                    ldt<128>(sn, gAh + k0, lda, tid);
                    ldt<BN>(sn + TILE_A, gBh + k0, K, tid);
                }
                asm volatile("cp.async.commit_group;" ::: "memory");
            }
#pragma unroll
            for (int s = 0; s < 4; s++) {
                const int cur = s & 1, nxt = cur ^ 1;
                if (s < 3) {
                    LOADFRAGS(nxt, st, s + 1);
                } else if (c + 1 < KT) {
                    // next chunk's s=0: stage c+1 is complete after this wait
                    asm volatile("cp.async.wait_group %0;" :: "n"(NS - 2) : "memory");
                    const uint32_t stn = sb + (uint32_t)((c + 1) % NS) * STAGE;
                    LOADFRAGS(nxt, stn, 0);
                }
#pragma unroll
                for (int mi = 0; mi < 4; mi++)
#pragma unroll
                    for (int bj = 0; bj < NBJ; bj++) {
                        mma16816(acc[mi][2 * bj],     ahf[cur][mi],
                                 bhf[cur][bj][0], bhf[cur][bj][2]);
                        mma16816(acc[mi][2 * bj + 1], ahf[cur][mi],
                                 bhf[cur][bj][1], bhf[cur][bj][3]);
                    }
            }
            __syncthreads();
        }
#undef LOADFRAGS
    } else {
        // ---- simple path (L3) ----
        for (int c = 0; c < KT; c++) {
            {
                const int cn = c + NS - 1;
                if (cn < KT) {
                    const uint32_t sn = sb + (uint32_t)(cn % NS) * STAGE;
                    const int k0 = cn * 64;
                    ldt<128>(sn, gAh + k0, lda, tid);
                    ldt<BN>(sn + TILE_A, gBh + k0, K, tid);
                }
                asm volatile("cp.async.commit_group;" ::: "memory");
            }
            asm volatile("cp.async.wait_group %0;" :: "n"(NS - 1) : "memory");
            __syncthreads();

            const uint32_t st = sb + (uint32_t)(c % NS) * STAGE;
#pragma unroll
            for (int s = 0; s < 4; s++) {
                uint32_t ahf[4][4], bhf[NBJ][4];
                const int c2 = s * 2 + hi16;
#pragma unroll
                for (int mi = 0; mi < 4; mi++) {
                    const uint32_t ao = arow[mi] * 128 + ((c2 ^ (arow[mi] & 7)) << 4);
                    ldsm4(ahf[mi], st + ao);
                }
#pragma unroll
                for (int bj = 0; bj < NBJ; bj++) {
                    const uint32_t bo = brow[bj] * 128 + ((c2 ^ (brow[bj] & 7)) << 4);
                    ldsm4(bhf[bj], st + TILE_A + bo);
                }
#pragma unroll
                for (int mi = 0; mi < 4; mi++)
#pragma unroll
                    for (int bj = 0; bj < NBJ; bj++) {
                        mma16816(acc[mi][2 * bj],     ahf[mi], bhf[bj][0], bhf[bj][2]);
                        mma16816(acc[mi][2 * bj + 1], ahf[mi], bhf[bj][1], bhf[bj][3]);
                    }
            }
            __syncthreads();
        }
    }

    // ---------------- epilogue ----------------
    const int rbase = (lane >> 2);
    const int cbase = (lane & 3) * 2;

#pragma unroll
    for (int mi = 0; mi < 4; mi++) {
#pragma unroll
        for (int nj = 0; nj < 2 * NBJ; nj++) {
#pragma unroll
            for (int half = 0; half < 2; half++) {
                const size_t m = (size_t)m0 + wm + mi * 16 + rbase + half * 8;
                const int col = n0 + wn + nj * 8 + cbase;
                float v0 = acc[mi][nj][2 * half];
                float v1 = acc[mi][nj][2 * half + 1];
                if (OMODE == 2) {
                    v0 = gelu_f(v0);
                    v1 = gelu_f(v1);
                    *reinterpret_cast<uint32_t*>(Ch + h * cHead + m * ldc + col) =
                        packh(__float2half_rn(v0), __float2half_rn(v1));
                } else {
                    *reinterpret_cast<float2*>(Cf + h * cHead + m * ldc + col) =
                        make_float2(v0, v1);
                }
            }
        }
    }
}

// ---------------- RMSNorm -> fp16 (hi only) ----------------
__global__ void rms_kernel(const float* __restrict__ x, const float* __restrict__ g,
                           fh* __restrict__ xh) {
    const int row = blockIdx.x, tid = threadIdx.x;
    const float4* xr = reinterpret_cast<const float4*>(x + (size_t)row * DTOT);
    float4 a = xr[tid], b = xr[tid + 256];
    float s = a.x * a.x + a.y * a.y + a.z * a.z + a.w * a.w +
              b.x * b.x + b.y * b.y + b.z * b.z + b.w * b.w;
#pragma unroll
    for (int o = 16; o; o >>= 1) s += __shfl_xor_sync(0xffffffffu, s, o);
    __shared__ float ws[8];
    __shared__ float srs;
    if ((tid & 31) == 0) ws[tid >> 5] = s;
    __syncthreads();
    if (tid == 0) {
        float t = 0.f;
#pragma unroll
        for (int i = 0; i < 8; i++) t += ws[i];
        srs = rsqrtf(t * (1.0f / DTOT) + 1.1920929e-7f);
    }
    __syncthreads();
    const float rs = srs;
    const float4* gr = reinterpret_cast<const float4*>(g);
    float4 ga = gr[tid], gb = gr[tid + 256];

    float va[8] = {a.x * rs * ga.x, a.y * rs * ga.y, a.z * rs * ga.z, a.w * rs * ga.w,
                   b.x * rs * gb.x, b.y * rs * gb.y, b.z * rs * gb.z, b.w * rs * gb.w};
    size_t base = (size_t)row * DTOT;
#pragma unroll
    for (int half = 0; half < 2; half++) {
        size_t o = base + (size_t)(tid + half * 256) * 4;
        uint32_t hp[2];
#pragma unroll
        for (int j = 0; j < 2; j++)
            hp[j] = packh(__float2half_rn(va[half * 4 + 2 * j]),
                          __float2half_rn(va[half * 4 + 2 * j + 1]));
        *reinterpret_cast<uint2*>(xh + o) = make_uint2(hp[0], hp[1]);
    }
}

// ---------------- weight transpose to fp16: W[h][K][N] -> O[h][N][K] ----------------
__global__ void wsplit_kernel(const float* __restrict__ W, int K, int N,
                              fh* __restrict__ Oh) {
    __shared__ float t[32][33];
    const int h = blockIdx.z;
    const int k0 = blockIdx.x * 32, n0 = blockIdx.y * 32;
    const int tx = threadIdx.x & 31, ty = threadIdx.x >> 5;
    const float* Wb = W + (size_t)h * K * N;
#pragma unroll
    for (int i = 0; i < 4; i++)
        t[ty + i * 8][tx] = Wb[(size_t)(k0 + ty + i * 8) * N + n0 + tx];
    __syncthreads();
#pragma unroll
    for (int i = 0; i < 4; i++) {
        int n = n0 + ty + i * 8, k = k0 + tx;
        size_t o = ((size_t)h * N + n) * K + k;
        Oh[o] = __float2half_rn(t[tx][ty + i * 8]);
    }
}

// ---------------- launch ----------------
extern "C" void kernel_launch(void* const* d_in, const int* in_sizes, int n_in,
                              void* d_out, int out_size) {
    const float* x  = (const float*)d_in[0];
    const float* g  = (const float*)d_in[1];
    const float* w0 = (const float*)d_in[2];
    const float* w1 = (const float*)d_in[3];
    const float* w2 = (const float*)d_in[4];
    const float* w3 = (const float*)d_in[5];
    float* out = (float*)d_out;

    fh *xh, *ah, *bh, *pw0, *pw1, *pw2, *pw3;
    cudaGetSymbolAddress((void**)&xh, g_xh);
    cudaGetSymbolAddress((void**)&ah, g_ah);
    cudaGetSymbolAddress((void**)&bh, g_bh);
    cudaGetSymbolAddress((void**)&pw0, g_w0);
    cudaGetSymbolAddress((void**)&pw1, g_w1);
    cudaGetSymbolAddress((void**)&pw2, g_w2);
    cudaGetSymbolAddress((void**)&pw3, g_w3);

    constexpr int SMEM256 = 3 * (128 * 128 + 256 * 128);  // 147456
    constexpr int SMEM128 = 3 * (128 * 128 + 128 * 128);  // 98304
    cudaFuncSetAttribute(hgemm_kernel<256, 2, 3, 1, 1>,
                         cudaFuncAttributeMaxDynamicSharedMemorySize, SMEM256);
    cudaFuncSetAttribute(hgemm_kernel<128, 1, 3, 2, 0>,
                         cudaFuncAttributeMaxDynamicSharedMemorySize, SMEM128);

    // prep
    rms_kernel<<<NTOK, 256>>>(x, g, xh);
    wsplit_kernel<<<dim3(DHEAD / 32, HID / 32, NHEAD), 256>>>(w0, DHEAD, HID, pw0);
    wsplit_kernel<<<dim3(HID / 32, HID / 32, NHEAD), 256>>>(w1, HID, HID, pw1);
    wsplit_kernel<<<dim3(HID / 32, HID / 32, NHEAD), 256>>>(w2, HID, HID, pw2);
    wsplit_kernel<<<dim3(HID / 32, DHEAD / 32, NHEAD), 256>>>(w3, HID, DHEAD, pw3);

    const size_t actHead = (size_t)NTOK * HID;

    // L0: a = gelu( xn[:,h] @ w0[h] )
    hgemm_kernel<256, 2, 3, 1, 1><<<dim3(NTOK / 128, HID / 256, NHEAD), 256, SMEM256>>>(
        xh, (size_t)DHEAD, DTOT, pw0, (size_t)HID * DHEAD, DHEAD,
        ah, nullptr, actHead, HID);
    // L1: b = gelu( a @ w1[h] )
    hgemm_kernel<256, 2, 3, 1, 1><<<dim3(NTOK / 128, HID / 256, NHEAD), 256, SMEM256>>>(
        ah, actHead, HID, pw1, (size_t)HID * HID, HID,
        bh, nullptr, actHead, HID);
    // L2: a = gelu( b @ w2[h] )
    hgemm_kernel<256, 2, 3, 1, 1><<<dim3(NTOK / 128, HID / 256, NHEAD), 256, SMEM256>>>(
        bh, actHead, HID, pw2, (size_t)HID * HID, HID,
        ah, nullptr, actHead, HID);
    // L3: out[:,h] = a @ w3[h]
    hgemm_kernel<128, 1, 3, 2, 0><<<dim3(NTOK / 128, DHEAD / 128, NHEAD), 256, SMEM128>>>(
        ah, actHead, HID, pw3, (size_t)DHEAD * HID, HID,
        nullptr, out, (size_t)DHEAD, DTOT);
}